// round 12
// baseline (speedup 1.0000x reference)
#include <cuda_runtime.h>
#include <cuda_bf16.h>
#include <cstdint>

// Problem constants
#define BATCH  4
#define SEQ    4096
#define DMODEL 1024
#define NHEAD  16
#define HDIM   64
#define MROWS  (BATCH*SEQ)          // 16384
#define NQKV   (3*DMODEL)           // 3072

// Scratch (device globals: allocation-free). hi/lo bf16 split operands,
// stored k-permuted (pair-granularity) for single-LDS.128 fragment loads.
__device__ float          g_qkv[(size_t)MROWS * NQKV];    // 192 MB f32
__device__ unsigned short g_xh [(size_t)MROWS * DMODEL];  // 32 MB
__device__ unsigned short g_xl [(size_t)MROWS * DMODEL];
__device__ unsigned short g_wqh[(size_t)NQKV  * DMODEL];
__device__ unsigned short g_wql[(size_t)NQKV  * DMODEL];
__device__ unsigned short g_wph[(size_t)DMODEL* DMODEL];
__device__ unsigned short g_wpl[(size_t)DMODEL* DMODEL];
__device__ unsigned short g_aoh[(size_t)MROWS * DMODEL];  // attn out (scrambled rows)
__device__ unsigned short g_aol[(size_t)MROWS * DMODEL];

// ---------------------------------------------------------------------------
// helpers
// ---------------------------------------------------------------------------
__device__ __forceinline__ float f2tf(float x) {
    uint32_t u;
    asm("cvt.rna.tf32.f32 %0, %1;" : "=r"(u) : "f"(x));
    return __uint_as_float(u);
}

__device__ __forceinline__ uint32_t smem_u32(const void* p) {
    uint32_t a;
    asm("{ .reg .u64 t; cvta.to.shared.u64 t, %1; cvt.u32.u64 %0, t; }" : "=r"(a) : "l"(p));
    return a;
}

// tf32 mma (attention kernel only)
__device__ __forceinline__ void mma8(float c[4], const float a[4], const float b[2]) {
    uint32_t A0 = __float_as_uint(a[0]), A1 = __float_as_uint(a[1]);
    uint32_t A2 = __float_as_uint(a[2]), A3 = __float_as_uint(a[3]);
    uint32_t B0 = __float_as_uint(b[0]), B1 = __float_as_uint(b[1]);
    asm volatile(
        "mma.sync.aligned.m16n8k8.row.col.f32.tf32.tf32.f32 "
        "{%0,%1,%2,%3}, {%4,%5,%6,%7}, {%8,%9}, {%0,%1,%2,%3};"
        : "+f"(c[0]), "+f"(c[1]), "+f"(c[2]), "+f"(c[3])
        : "r"(A0), "r"(A1), "r"(A2), "r"(A3), "r"(B0), "r"(B1));
}

// bf16 mma m16n8k16, f32 accum
__device__ __forceinline__ void mma16(float c[4], uint32_t a0, uint32_t a1,
                                      uint32_t a2, uint32_t a3,
                                      uint32_t b0, uint32_t b1) {
    asm volatile(
        "mma.sync.aligned.m16n8k16.row.col.f32.bf16.bf16.f32 "
        "{%0,%1,%2,%3}, {%4,%5,%6,%7}, {%8,%9}, {%0,%1,%2,%3};"
        : "+f"(c[0]), "+f"(c[1]), "+f"(c[2]), "+f"(c[3])
        : "r"(a0), "r"(a1), "r"(a2), "r"(a3), "r"(b0), "r"(b1));
}

__device__ __forceinline__ void cp16(uint32_t dst, const void* src) {
    asm volatile("cp.async.cg.shared.global [%0], [%1], 16;" :: "r"(dst), "l"(src));
}
__device__ __forceinline__ void cp_commit() {
    asm volatile("cp.async.commit_group;" ::: "memory");
}
template<int N> __device__ __forceinline__ void cp_wait() {
    asm volatile("cp.async.wait_group %0;" :: "n"(N) : "memory");
}

// split 8 f32 (one 16B output chunk worth) into hi/lo bf16, packed
__device__ __forceinline__ void split8(const float* v, uint4& uh, uint4& ul) {
    unsigned short hs[8], ls[8];
    #pragma unroll
    for (int j = 0; j < 8; j++) {
        __nv_bfloat16 h = __float2bfloat16(v[j]);              // rn
        float hf = __bfloat162float(h);
        __nv_bfloat16 l = __float2bfloat16(v[j] - hf);
        hs[j] = __bfloat16_as_ushort(h);
        ls[j] = __bfloat16_as_ushort(l);
    }
    uh = make_uint4((uint32_t)hs[0] | ((uint32_t)hs[1] << 16),
                    (uint32_t)hs[2] | ((uint32_t)hs[3] << 16),
                    (uint32_t)hs[4] | ((uint32_t)hs[5] << 16),
                    (uint32_t)hs[6] | ((uint32_t)hs[7] << 16));
    ul = make_uint4((uint32_t)ls[0] | ((uint32_t)ls[1] << 16),
                    (uint32_t)ls[2] | ((uint32_t)ls[3] << 16),
                    (uint32_t)ls[4] | ((uint32_t)ls[5] << 16),
                    (uint32_t)ls[6] | ((uint32_t)ls[7] << 16));
}

// ---------------------------------------------------------------------------
// conv_split: f32 row (K=1024) -> hi/lo bf16 rows, pair-permuted layout.
// Per k32 chunk c (64B out), slot tg (16B) holds logical pairs
// {(g0,tg),(g0,tg+4),(g1,tg),(g1,tg+4)} = ks {2t,2t+1, 2t+8,2t+9, 2t+16,
// 2t+17, 2t+24, 2t+25} with t=tg.  One thread per (row, c, tg).
// ---------------------------------------------------------------------------
__global__ __launch_bounds__(256)
void conv_split(const float* __restrict__ src, unsigned short* __restrict__ hi,
                unsigned short* __restrict__ lo, int nunits)
{
    int F = blockIdx.x * 256 + threadIdx.x;
    if (F >= nunits) return;
    int row = F >> 7;
    int u   = F & 127;
    int c = u >> 2, tg = u & 3;
    const float* s = src + (size_t)row * 1024 + c * 32;
    float v[8];
    #pragma unroll
    for (int g = 0; g < 2; g++) {
        v[g*4+0] = s[g*16 + 2*tg    ];
        v[g*4+1] = s[g*16 + 2*tg + 1];
        v[g*4+2] = s[g*16 + 2*tg + 8];
        v[g*4+3] = s[g*16 + 2*tg + 9];
    }
    uint4 uh, ul;
    split8(v, uh, ul);
    const size_t boff = (size_t)row * 2048 + c * 64 + tg * 16;
    *reinterpret_cast<uint4*>(reinterpret_cast<uint8_t*>(hi) + boff) = uh;
    *reinterpret_cast<uint4*>(reinterpret_cast<uint8_t*>(lo) + boff) = ul;
}

// ---------------------------------------------------------------------------
// bf16 split GEMM: C = A*B^T (+bias), A,B given as hi/lo bf16 permuted rows.
// C = Ahi*Bhi + Ahi*Blo + Alo*Bhi  (lo*lo dropped; ~2^-16 accurate).
// BM=128, BN=128, BK=32 per stage; stage = Ahi|Alo|Bhi|Blo 8KB each = 32KB.
// 8 warps (4Mx2N, warp 32x64), 3-stage cp.async ring, 2 CTAs/SM.
// Iter: [ld AH, P1=AH*Bhi] -> bar -> [P2=AH*Blo] -> [load kt+2, wait<1>]
//       -> [ld AL, P3=AL*Bhi].
// ---------------------------------------------------------------------------
#define BM2  128
#define BN2  128
#define STGB 32768
#define SM_GEMM (3*STGB)            // 96 KB

template<int MODE>
__global__ __launch_bounds__(256, 2)
void gemm_bf(const unsigned short* __restrict__ Ah, const unsigned short* __restrict__ Al,
             const unsigned short* __restrict__ Bh, const unsigned short* __restrict__ Bl,
             const float* __restrict__ bias, float* __restrict__ C, int ldc)
{
    extern __shared__ char smc[];
    const uint32_t sb = smem_u32(smc);
    const int tid  = threadIdx.x;
    const int warp = tid >> 5, lane = tid & 31;
    const int gp   = lane >> 2, tg = lane & 3;
    const int wm   = (warp & 3) * 32;        // 4 warps across M
    const int wn   = (warp >> 2) * 64;       // 2 warps across N
    const int bm   = blockIdx.y * BM2;
    const int bn   = blockIdx.x * BN2;

    const uint8_t* pAh = reinterpret_cast<const uint8_t*>(Ah);
    const uint8_t* pAl = reinterpret_cast<const uint8_t*>(Al);
    const uint8_t* pBh = reinterpret_cast<const uint8_t*>(Bh);
    const uint8_t* pBl = reinterpret_cast<const uint8_t*>(Bl);

    // stage layout (bytes): [Ahi 8K][Alo 8K][Bhi 8K][Blo 8K]
    auto load_stage = [&](int buf, int kt) {
        const uint32_t base = sb + buf * STGB;
        const int ko = kt * 64;              // byte offset within 2048B row
        #pragma unroll
        for (int i = 0; i < 2; i++) {        // 128 rows x 64B per set
            int t = tid + 256*i; int row = t >> 2, sl = t & 3;
            const uint32_t so = row*64 + ((sl ^ (row & 3)) << 4);
            const size_t goA = (size_t)(bm + row)*2048 + ko + sl*16;
            const size_t goB = (size_t)(bn + row)*2048 + ko + sl*16;
            cp16(base +         so, pAh + goA);
            cp16(base +  8192 + so, pAl + goA);
            cp16(base + 16384 + so, pBh + goB);
            cp16(base + 24576 + so, pBl + goB);
        }
    };

    // A-fragment loader: 4x LDS.128 for one set (setoff = 0:hi, 8192:lo)
    auto load_af = [&](uint4* A0, uint4* A8, int buf, int setoff) {
        const uint8_t* As = reinterpret_cast<const uint8_t*>(smc) + buf*STGB + setoff;
        #pragma unroll
        for (int mt = 0; mt < 2; mt++) {
            const int R0 = wm + mt*16 + gp;
            const int co = ((tg ^ (R0 & 3)) << 4);       // same for R0+8
            A0[mt] = *reinterpret_cast<const uint4*>(As + R0*64 + co);
            A8[mt] = *reinterpret_cast<const uint4*>(As + (R0+8)*64 + co);
        }
    };

    float acc[2][8][4];
    #pragma unroll
    for (int i = 0; i < 2; i++)
        #pragma unroll
        for (int j = 0; j < 8; j++)
            #pragma unroll
            for (int k = 0; k < 4; k++) acc[i][j][k] = 0.f;

    // one half of a product (4 of 8 n-tiles): 4 B LDS.128 + 16 MMAs
    auto mma_half = [&](const uint4* A0, const uint4* A8, int buf, int bsetoff, int half) {
        const uint8_t* Bs = reinterpret_cast<const uint8_t*>(smc) + buf*STGB + bsetoff;
        uint4 Bf[4];
        #pragma unroll
        for (int j = 0; j < 4; j++) {
            const int R = wn + (half*4 + j)*8 + gp;
            Bf[j] = *reinterpret_cast<const uint4*>(Bs + R*64 + ((tg ^ (R & 3)) << 4));
        }
        #pragma unroll
        for (int j = 0; j < 4; j++) {        // k-group 0
            const int nt = half*4 + j;
            #pragma unroll
            for (int mt = 0; mt < 2; mt++)
                mma16(acc[mt][nt], A0[mt].x, A8[mt].x, A0[mt].y, A8[mt].y,
                      Bf[j].x, Bf[j].y);
        }
        #pragma unroll
        for (int j = 0; j < 4; j++) {        // k-group 1
            const int nt = half*4 + j;
            #pragma unroll
            for (int mt = 0; mt < 2; mt++)
                mma16(acc[mt][nt], A0[mt].z, A8[mt].z, A0[mt].w, A8[mt].w,
                      Bf[j].z, Bf[j].w);
        }
    };

    load_stage(0, 0); cp_commit();
    load_stage(1, 1); cp_commit();
    cp_wait<1>();            // stage 0 resident
    __syncthreads();

    uint4 A0[2], A8[2];
    const int NI = DMODEL / 32;    // 32
    int buf = 0;
    for (int kt = 0; kt < NI; kt++) {
        // P1 = Ahi * Bhi
        load_af(A0, A8, buf, 0);
        mma_half(A0, A8, buf, 16384, 0);
        mma_half(A0, A8, buf, 16384, 1);

        __syncthreads();                     // stage kt-1 drained by all warps

        // P2 = Ahi * Blo (operands resident -> tensor-first post-barrier)
        mma_half(A0, A8, buf, 24576, 0);
        mma_half(A0, A8, buf, 24576, 1);

        // cp.async prefix + wait overlap P2's HMMA drain
        if (kt + 2 < NI) load_stage((buf + 2) % 3, kt + 2);
        cp_commit();
        cp_wait<1>();                        // stage kt+1 resident (kt+2 streams)

        // P3 = Alo * Bhi
        load_af(A0, A8, buf, 8192);
        mma_half(A0, A8, buf, 16384, 0);
        mma_half(A0, A8, buf, 16384, 1);

        buf = (buf + 1) % 3;
    }

    // epilogue: direct float2 stores
    #pragma unroll
    for (int mt = 0; mt < 2; mt++) {
        #pragma unroll
        for (int nt = 0; nt < 8; nt++) {
            const int col = bn + wn + nt*8 + 2*tg;
            float bx = 0.f, by = 0.f;
            if (MODE == 1) {
                float2 bv = *reinterpret_cast<const float2*>(&bias[col]);
                bx = bv.x; by = bv.y;
            }
            #pragma unroll
            for (int rr = 0; rr < 2; rr++) {
                const int row = bm + wm + mt*16 + gp + rr*8;
                *reinterpret_cast<float2*>(&C[(size_t)row*ldc + col]) =
                    make_float2(acc[mt][nt][rr*2] + bx, acc[mt][nt][rr*2+1] + by);
            }
        }
    }
}

// ---------------------------------------------------------------------------
// Per-token head attention (einsum over HEADS, per token). One warp/token.
// Writes g_aoh/g_aol (hi/lo bf16 split, pair-permuted) in the scrambled
// swapaxes row layout so the proj GEMM consumes it directly.
// ---------------------------------------------------------------------------
#define AWARPS 8
#define ATTN_SMEM_FLOATS (AWARPS * (3*16*68 + 16*20))   // 28672 floats = 114688 B

__global__ __launch_bounds__(AWARPS*32)
void attn_tf32(float* __restrict__ dummy)
{
    extern __shared__ float sm[];
    const int warp = threadIdx.x >> 5, lane = threadIdx.x & 31;
    const int gp = lane >> 2, tg = lane & 3;

    float* wsm = sm + warp * (3*16*68 + 16*20);
    float (*Qs)[68] = reinterpret_cast<float(*)[68]>(wsm);
    float (*Ks)[68] = reinterpret_cast<float(*)[68]>(wsm + 1088);
    float (*Vs)[68] = reinterpret_cast<float(*)[68]>(wsm + 2176);
    float (*Ps)[20] = reinterpret_cast<float(*)[20]>(wsm + 3264);
    (void)dummy;

    const int token = blockIdx.x * AWARPS + warp;
    const float* base = g_qkv + (size_t)token * NQKV;
    const float scale = 0.125f;   // HD^-0.5

    #pragma unroll
    for (int j = 0; j < 8; j++) {
        const int c4 = lane + j*32;
        const int h  = c4 >> 4;
        const int d4 = (c4 & 15) * 4;
        float4 q = *reinterpret_cast<const float4*>(base + c4*4);
        q.x=f2tf(q.x*scale); q.y=f2tf(q.y*scale); q.z=f2tf(q.z*scale); q.w=f2tf(q.w*scale);
        *reinterpret_cast<float4*>(&Qs[h][d4]) = q;
        float4 k = *reinterpret_cast<const float4*>(base + 1024 + c4*4);
        k.x=f2tf(k.x); k.y=f2tf(k.y); k.z=f2tf(k.z); k.w=f2tf(k.w);
        *reinterpret_cast<float4*>(&Ks[h][d4]) = k;
        float4 v = *reinterpret_cast<const float4*>(base + 2048 + c4*4);
        v.x=f2tf(v.x); v.y=f2tf(v.y); v.z=f2tf(v.z); v.w=f2tf(v.w);
        *reinterpret_cast<float4*>(&Vs[h][d4]) = v;
    }
    __syncwarp();

    // S = Q K^T : m16 x n16 (2 tiles) x k64 (8 steps)
    float s[2][4] = {{0.f,0.f,0.f,0.f},{0.f,0.f,0.f,0.f}};
    #pragma unroll
    for (int ks = 0; ks < 8; ks++) {
        const int c0 = ks*8 + tg, c1 = c0 + 4;
        float a[4] = { Qs[gp][c0], Qs[gp+8][c0], Qs[gp][c1], Qs[gp+8][c1] };
        #pragma unroll
        for (int nt = 0; nt < 2; nt++) {
            float b[2] = { Ks[nt*8+gp][c0], Ks[nt*8+gp][c1] };
            mma8(s[nt], a, b);
        }
    }

    // softmax over g (exact)
    float m0 = fmaxf(fmaxf(s[0][0], s[0][1]), fmaxf(s[1][0], s[1][1]));
    float m1 = fmaxf(fmaxf(s[0][2], s[0][3]), fmaxf(s[1][2], s[1][3]));
    m0 = fmaxf(m0, __shfl_xor_sync(0xffffffffu, m0, 1));
    m0 = fmaxf(m0, __shfl_xor_sync(0xffffffffu, m0, 2));
    m1 = fmaxf(m1, __shfl_xor_sync(0xffffffffu, m1, 1));
    m1 = fmaxf(m1, __shfl_xor_sync(0xffffffffu, m1, 2));
    #pragma unroll
    for (int nt = 0; nt < 2; nt++) {
        s[nt][0] = __expf(s[nt][0] - m0);
        s[nt][1] = __expf(s[nt][1] - m0);
        s[nt][2] = __expf(s[nt][2] - m1);
        s[nt][3] = __expf(s[nt][3] - m1);
    }
    float l0 = s[0][0] + s[0][1] + s[1][0] + s[1][1];
    float l1 = s[0][2] + s[0][3] + s[1][2] + s[1][3];
    l0 += __shfl_xor_sync(0xffffffffu, l0, 1);
    l0 += __shfl_xor_sync(0xffffffffu, l0, 2);
    l1 += __shfl_xor_sync(0xffffffffu, l1, 1);
    l1 += __shfl_xor_sync(0xffffffffu, l1, 2);
    const float r0 = 1.f / l0, r1 = 1.f / l1;

    #pragma unroll
    for (int nt = 0; nt < 2; nt++) {
        *reinterpret_cast<float2*>(&Ps[gp  ][nt*8 + 2*tg]) =
            make_float2(f2tf(s[nt][0]*r0), f2tf(s[nt][1]*r0));
        *reinterpret_cast<float2*>(&Ps[gp+8][nt*8 + 2*tg]) =
            make_float2(f2tf(s[nt][2]*r1), f2tf(s[nt][3]*r1));
    }
    __syncwarp();

    // O = P V : m16 x n64 (8 tiles) x k16 (2 steps)
    float o[8][4];
    #pragma unroll
    for (int nt = 0; nt < 8; nt++)
        #pragma unroll
        for (int k = 0; k < 4; k++) o[nt][k] = 0.f;
    #pragma unroll
    for (int ks = 0; ks < 2; ks++) {
        const int c0 = ks*8 + tg, c1 = c0 + 4;
        float a[4] = { Ps[gp][c0], Ps[gp+8][c0], Ps[gp][c1], Ps[gp+8][c1] };
        #pragma unroll
        for (int nt = 0; nt < 8; nt++) {
            float b[2] = { Vs[c0][nt*8+gp], Vs[c1][nt*8+gp] };
            mma8(o[nt], a, b);
        }
    }

    // stage raw f32 O into smem, then split hi/lo + permuted write
    float (*Os)[68] = Qs;   // Qs region is free now
    #pragma unroll
    for (int rr = 0; rr < 2; rr++)
        #pragma unroll
        for (int nt = 0; nt < 8; nt++)
            *reinterpret_cast<float2*>(&Os[gp + 8*rr][nt*8 + 2*tg]) =
                make_float2(o[nt][rr*2], o[nt][rr*2+1]);
    __syncwarp();

    const int bidx = token >> 12;
    const int n    = token & 4095;
    const int cg0  = 2 * (n & 15);           // first global k32-chunk of this token's span
    #pragma unroll
    for (int i = 0; i < 4; i++) {
        const int idx = lane + 32*i;         // 0..127 = 16 h x 2 chunks x 4 slots
        const int h = idx >> 3;
        const int c = (idx >> 2) & 1;
        const int t = idx & 3;
        const float* row = Os[h] + c*32;
        float v[8];
        #pragma unroll
        for (int g = 0; g < 2; g++) {
            v[g*4+0] = row[g*16 + 2*t    ];
            v[g*4+1] = row[g*16 + 2*t + 1];
            v[g*4+2] = row[g*16 + 2*t + 8];
            v[g*4+3] = row[g*16 + 2*t + 9];
        }
        uint4 uh, ul;
        split8(v, uh, ul);
        const size_t drow = (size_t)(bidx*4096 + h*256 + (n >> 4));
        const size_t boff = drow*2048 + (size_t)(cg0 + c)*64 + t*16;
        *reinterpret_cast<uint4*>(reinterpret_cast<uint8_t*>(g_aoh) + boff) = uh;
        *reinterpret_cast<uint4*>(reinterpret_cast<uint8_t*>(g_aol) + boff) = ul;
    }
}

// ---------------------------------------------------------------------------
// launcher
// ---------------------------------------------------------------------------
extern "C" void kernel_launch(void* const* d_in, const int* in_sizes, int n_in,
                              void* d_out, int out_size)
{
    (void)in_sizes; (void)n_in; (void)out_size;
    const float* x      = (const float*)d_in[0];  // [4,4096,1024]
    const float* w_qkv  = (const float*)d_in[1];  // [3072,1024]
    const float* w_proj = (const float*)d_in[2];  // [1024,1024]
    const float* b_proj = (const float*)d_in[3];  // [1024]
    float* out = (float*)d_out;                   // [4,4096,1024]

    cudaFuncSetAttribute(gemm_bf<0>, cudaFuncAttributeMaxDynamicSharedMemorySize, SM_GEMM);
    cudaFuncSetAttribute(gemm_bf<1>, cudaFuncAttributeMaxDynamicSharedMemorySize, SM_GEMM);
    cudaFuncSetAttribute(attn_tf32, cudaFuncAttributeMaxDynamicSharedMemorySize,
                         ATTN_SMEM_FLOATS * (int)sizeof(float));

    unsigned short *pxh, *pxl, *pwqh, *pwql, *pwph, *pwpl, *paoh, *paol;
    cudaGetSymbolAddress((void**)&pxh,  g_xh);
    cudaGetSymbolAddress((void**)&pxl,  g_xl);
    cudaGetSymbolAddress((void**)&pwqh, g_wqh);
    cudaGetSymbolAddress((void**)&pwql, g_wql);
    cudaGetSymbolAddress((void**)&pwph, g_wph);
    cudaGetSymbolAddress((void**)&pwpl, g_wpl);
    cudaGetSymbolAddress((void**)&paoh, g_aoh);
    cudaGetSymbolAddress((void**)&paol, g_aol);
    float* pqkv;
    cudaGetSymbolAddress((void**)&pqkv, g_qkv);

    // 0) split (hi/lo bf16) + k-permute inputs
    conv_split<<<MROWS*128/256, 256>>>(x,      pxh,  pxl,  MROWS*128);
    conv_split<<<NQKV *128/256, 256>>>(w_qkv,  pwqh, pwql, NQKV*128);
    conv_split<<<DMODEL*128/256, 256>>>(w_proj, pwph, pwpl, DMODEL*128);

    // 1) QKV projection: g_qkv = x @ w_qkv^T  (f32 out)
    gemm_bf<0><<<dim3(NQKV/BN2, MROWS/BM2), 256, SM_GEMM>>>(
        pxh, pxl, pwqh, pwql, nullptr, pqkv, NQKV);

    // 2) per-token head attention -> g_aoh/g_aol (scrambled + split + permuted)
    attn_tf32<<<MROWS/AWARPS, AWARPS*32, ATTN_SMEM_FLOATS * sizeof(float)>>>(nullptr);

    // 3) output projection: out = ao @ w_proj^T + b_proj
    gemm_bf<1><<<dim3(DMODEL/BN2, MROWS/BM2), 256, SM_GEMM>>>(
        paoh, paol, pwph, pwpl, b_proj, out, DMODEL);
}

// round 13
// speedup vs baseline: 1.4074x; 1.4074x over previous
#include <cuda_runtime.h>
#include <cstdint>

// Problem constants
#define BATCH  4
#define SEQ    4096
#define DMODEL 1024
#define NHEAD  16
#define HDIM   64
#define MROWS  (BATCH*SEQ)          // 16384
#define NQKV   (3*DMODEL)           // 3072

// Scratch (device globals: allocation-free)
__device__ float g_qkv[(size_t)MROWS * NQKV];   // 192 MB (logical layout)
__device__ float g_ao [(size_t)MROWS * DMODEL]; //  64 MB (scrambled + k-permuted + rounded)
__device__ float g_x  [(size_t)MROWS * DMODEL]; //  64 MB (rounded + k-permuted x)
__device__ float g_wq [(size_t)NQKV  * DMODEL]; //  12 MB (rounded + k-permuted w_qkv)
__device__ float g_wp [(size_t)DMODEL* DMODEL]; //   4 MB (rounded + k-permuted w_proj)

// ---------------------------------------------------------------------------
// helpers
// ---------------------------------------------------------------------------
__device__ __forceinline__ float f2tf(float x) {
    uint32_t u;
    asm("cvt.rna.tf32.f32 %0, %1;" : "=r"(u) : "f"(x));
    return __uint_as_float(u);
}

__device__ __forceinline__ uint32_t smem_u32(const void* p) {
    uint32_t a;
    asm("{ .reg .u64 t; cvta.to.shared.u64 t, %1; cvt.u32.u64 %0, t; }" : "=r"(a) : "l"(p));
    return a;
}

__device__ __forceinline__ void mma8(float c[4], const float a[4], const float b[2]) {
    uint32_t A0 = __float_as_uint(a[0]), A1 = __float_as_uint(a[1]);
    uint32_t A2 = __float_as_uint(a[2]), A3 = __float_as_uint(a[3]);
    uint32_t B0 = __float_as_uint(b[0]), B1 = __float_as_uint(b[1]);
    asm volatile(
        "mma.sync.aligned.m16n8k8.row.col.f32.tf32.tf32.f32 "
        "{%0,%1,%2,%3}, {%4,%5,%6,%7}, {%8,%9}, {%0,%1,%2,%3};"
        : "+f"(c[0]), "+f"(c[1]), "+f"(c[2]), "+f"(c[3])
        : "r"(A0), "r"(A1), "r"(A2), "r"(A3), "r"(B0), "r"(B1));
}

__device__ __forceinline__ void cp16(uint32_t dst, const void* src) {
    asm volatile("cp.async.cg.shared.global [%0], [%1], 16;" :: "r"(dst), "l"(src));
}
__device__ __forceinline__ void cp_commit() {
    asm volatile("cp.async.commit_group;" ::: "memory");
}
template<int N> __device__ __forceinline__ void cp_wait() {
    asm volatile("cp.async.wait_group %0;" :: "n"(N) : "memory");
}

__device__ __forceinline__ void mbar_init(uint32_t a, uint32_t n) {
    asm volatile("mbarrier.init.shared.b64 [%0], %1;" :: "r"(a), "r"(n) : "memory");
}
__device__ __forceinline__ void mbar_arrive(uint32_t a) {
    asm volatile("mbarrier.arrive.shared::cta.b64 _, [%0];" :: "r"(a) : "memory");
}
__device__ __forceinline__ void mbar_wait(uint32_t a, uint32_t parity) {
    asm volatile(
        "{\n\t.reg .pred P;\n\t"
        "WL%=:\n\t"
        "mbarrier.try_wait.parity.shared::cta.b64 P, [%0], %1, 0x989680;\n\t"
        "@P bra WD%=;\n\t"
        "bra WL%=;\n\t"
        "WD%=:\n\t}"
        :: "r"(a), "r"(parity) : "memory");
}

// ---------------------------------------------------------------------------
// conv_perm: round to tf32 (rna) + intra-16 k-permutation, K=1024 rows.
// ---------------------------------------------------------------------------
__global__ __launch_bounds__(256)
void conv_perm(const float* __restrict__ src, float* __restrict__ dst, int nf4)
{
    int F = blockIdx.x * 256 + threadIdx.x;
    if (F >= nf4) return;
    int row = F >> 8;
    int p4  = F & 255;
    int g = p4 >> 2, qq = p4 & 3;
    const float* s = src + (size_t)row * 1024 + g * 16 + qq;
    float4 v;
    v.x = f2tf(s[0]); v.y = f2tf(s[4]); v.z = f2tf(s[8]); v.w = f2tf(s[12]);
    *reinterpret_cast<float4*>(dst + (size_t)row * 1024 + p4 * 4) = v;
}

// ---------------------------------------------------------------------------
// cp.async TF32 GEMM: C[M,N] = A[M,1024]*B[N,1024]^T (+bias)
// BM=128, BN=128, BK=32 (2 k16 panels), 8 warps (4Mx2N, warp 32x64),
// 3-stage ring, 2 CTAs/SM. NO __syncthreads in the mainloop: per-slot
// ready/free mbarriers (256 arrivals) let warps free-run with <=1 iter
// skew, so one warp's HMMA stream covers another's cp.async window.
//   iter kt: wait ready[buf] -> afrags -> mma p0
//            -> wait free[s2] -> load_stage(kt+2) -> commit, wait<1>,
//               arrive ready[nbuf] -> mma p1 -> arrive free[buf]
// ---------------------------------------------------------------------------
#define BM2  128
#define BN2  128
#define STGB 32768                  // stage: A 2x8KB + B 2x8KB
#define SM_GEMM (3*STGB + 64)       // + 6 mbarriers

template<int MODE>
__global__ __launch_bounds__(256, 2)
void gemm_cp(const float* __restrict__ A, const float* __restrict__ B,
             const float* __restrict__ bias, float* __restrict__ C, int ldc)
{
    extern __shared__ char smc[];
    const uint32_t sb = smem_u32(smc);
    const int tid  = threadIdx.x;
    const int warp = tid >> 5, lane = tid & 31;
    const int gp   = lane >> 2, tg = lane & 3;
    const int wm   = (warp & 3) * 32;        // 4 warps across M
    const int wn   = (warp >> 2) * 64;       // 2 warps across N
    const int bm   = blockIdx.y * BM2;
    const int bn   = blockIdx.x * BN2;

    const uint32_t mbR = sb + 3*STGB;        // ready[s] at +8s
    const uint32_t mbF = sb + 3*STGB + 24;   // free[s]  at +8s

    auto load_stage = [&](int buf, int kt) {
        const uint32_t base = sb + buf * STGB;
        #pragma unroll
        for (int p = 0; p < 2; p++) {
            #pragma unroll
            for (int i = 0; i < 2; i++) {                // A: 128 rows x 64B
                int t = tid + 256*i; int row = t >> 2, c4 = t & 3;
                cp16(base + p*8192 + row*64 + ((c4 ^ (row & 3)) << 4),
                     A + (size_t)(bm + row)*DMODEL + kt*32 + p*16 + c4*4);
            }
            #pragma unroll
            for (int i = 0; i < 2; i++) {                // B: 128 rows x 64B
                int t = tid + 256*i; int row = t >> 2, c4 = t & 3;
                cp16(base + 16384 + p*8192 + row*64 + ((c4 ^ (row & 3)) << 4),
                     B + (size_t)(bn + row)*DMODEL + kt*32 + p*16 + c4*4);
            }
        }
    };

    // A-fragment loader: 4x LDS.128 for one k16 panel
    auto load_afrag = [&](float4* A0, float4* A8, int buf, int p) {
        const float* As = reinterpret_cast<const float*>(smc + buf*STGB + p*8192);
        #pragma unroll
        for (int mt = 0; mt < 2; mt++) {
            const int R0 = wm + mt*16 + gp;
            const int co = ((tg ^ (R0 & 3)) << 2);       // same for R0+8
            A0[mt] = *reinterpret_cast<const float4*>(As + R0*16 + co);
            A8[mt] = *reinterpret_cast<const float4*>(As + (R0+8)*16 + co);
        }
    };

    float acc[2][8][4];
    #pragma unroll
    for (int i = 0; i < 2; i++)
        #pragma unroll
        for (int j = 0; j < 8; j++)
            #pragma unroll
            for (int k = 0; k < 4; k++) acc[i][j][k] = 0.f;

    // one HALF of a panel (4 of 8 n-tiles): B 4x LDS.128 + 16 MMAs,
    // k-sub passes split so same-acc reuse distance stays 8
    auto mma_half = [&](const float4* A0, const float4* A8, int buf, int p, int half) {
        const float* Bs = reinterpret_cast<const float*>(smc + buf*STGB + 16384 + p*8192);
        float4 Bf[4];
        #pragma unroll
        for (int j = 0; j < 4; j++) {
            const int R = wn + (half*4 + j)*8 + gp;
            Bf[j] = *reinterpret_cast<const float4*>(Bs + R*16 + ((tg ^ (R & 3)) << 2));
        }
        #pragma unroll
        for (int j = 0; j < 4; j++) {
            const int nt = half*4 + j;
            #pragma unroll
            for (int mt = 0; mt < 2; mt++) {
                const float a0[4] = { A0[mt].x, A8[mt].x, A0[mt].y, A8[mt].y };
                const float b0[2] = { Bf[j].x, Bf[j].y };
                mma8(acc[mt][nt], a0, b0);
            }
        }
        #pragma unroll
        for (int j = 0; j < 4; j++) {
            const int nt = half*4 + j;
            #pragma unroll
            for (int mt = 0; mt < 2; mt++) {
                const float a1[4] = { A0[mt].z, A8[mt].z, A0[mt].w, A8[mt].w };
                const float b1[2] = { Bf[j].z, Bf[j].w };
                mma8(acc[mt][nt], a1, b1);
            }
        }
    };

    // ---- prologue: mbarrier init + first two stages in flight ----
    if (tid < 6) mbar_init(mbR + tid*8, 256);
    __syncthreads();                         // init visible (only CTA-wide sync)

    load_stage(0, 0); cp_commit();
    load_stage(1, 1); cp_commit();
    cp_wait<1>();                            // own stage-0 loads done
    mbar_arrive(mbR + 0);                    // ready[0]
    mbar_arrive(mbF + 16);                   // free[2] pre-armed

    float4 Aa0[2], Aa8[2], Ab0[2], Ab8[2];
    uint32_t prR = 0, prF = 0;               // per-slot parity bitfields

    const int NI = DMODEL / 32;    // 32
    int buf = 0;
    for (int kt = 0; kt < NI; kt++) {
        const int nbuf = (buf + 1 < 3) ? buf + 1 : 0;
        const int s2   = (buf + 2 < 3) ? buf + 2 : buf - 1;

        // stage kt fully resident (ALL threads' cp.async done) — clean acquire
        mbar_wait(mbR + buf*8, (prR >> buf) & 1);
        prR ^= (1u << buf);

        load_afrag(Aa0, Aa8, buf, 0);
        load_afrag(Ab0, Ab8, buf, 1);
        mma_half(Aa0, Aa8, buf, 0, 0);
        mma_half(Aa0, Aa8, buf, 0, 1);

        if (kt + 2 < NI) {
            // slot s2 (held stage kt-1) drained by ALL threads
            mbar_wait(mbF + s2*8, (prF >> s2) & 1);
            prF ^= (1u << s2);
            load_stage(s2, kt + 2);
        }
        cp_commit();
        cp_wait<1>();                        // own stage kt+1 loads done
        if (kt + 1 < NI) mbar_arrive(mbR + nbuf*8);

        mma_half(Ab0, Ab8, buf, 1, 0);
        mma_half(Ab0, Ab8, buf, 1, 1);
        mbar_arrive(mbF + buf*8);            // reads of stage kt finished
        buf = nbuf;
    }

    // epilogue: direct float2 stores (acc is register-private; no sync needed)
    #pragma unroll
    for (int mt = 0; mt < 2; mt++) {
        #pragma unroll
        for (int nt = 0; nt < 8; nt++) {
            const int col = bn + wn + nt*8 + 2*tg;
            float bx = 0.f, by = 0.f;
            if (MODE == 1) {
                float2 bv = *reinterpret_cast<const float2*>(&bias[col]);
                bx = bv.x; by = bv.y;
            }
            #pragma unroll
            for (int rr = 0; rr < 2; rr++) {
                const int row = bm + wm + mt*16 + gp + rr*8;
                *reinterpret_cast<float2*>(&C[(size_t)row*ldc + col]) =
                    make_float2(acc[mt][nt][rr*2] + bx, acc[mt][nt][rr*2+1] + by);
            }
        }
    }
}

// ---------------------------------------------------------------------------
// Per-token head attention (einsum over HEADS, per token). One warp/token.
// Writes g_ao in the scrambled swapaxes layout, tf32-rounded AND k-permuted.
// ---------------------------------------------------------------------------
#define AWARPS 8
#define ATTN_SMEM_FLOATS (AWARPS * (3*16*68 + 16*20))   // 28672 floats = 114688 B

__global__ __launch_bounds__(AWARPS*32)
void attn_tf32(float* __restrict__ dummy)
{
    extern __shared__ float sm[];
    const int warp = threadIdx.x >> 5, lane = threadIdx.x & 31;
    const int gp = lane >> 2, tg = lane & 3;

    float* wsm = sm + warp * (3*16*68 + 16*20);
    float (*Qs)[68] = reinterpret_cast<float(*)[68]>(wsm);
    float (*Ks)[68] = reinterpret_cast<float(*)[68]>(wsm + 1088);
    float (*Vs)[68] = reinterpret_cast<float(*)[68]>(wsm + 2176);
    float (*Ps)[20] = reinterpret_cast<float(*)[20]>(wsm + 3264);
    (void)dummy;

    const int token = blockIdx.x * AWARPS + warp;
    const float* base = g_qkv + (size_t)token * NQKV;
    const float scale = 0.125f;   // HD^-0.5

    #pragma unroll
    for (int j = 0; j < 8; j++) {
        const int c4 = lane + j*32;
        const int h  = c4 >> 4;
        const int d4 = (c4 & 15) * 4;
        float4 q = *reinterpret_cast<const float4*>(base + c4*4);
        q.x=f2tf(q.x*scale); q.y=f2tf(q.y*scale); q.z=f2tf(q.z*scale); q.w=f2tf(q.w*scale);
        *reinterpret_cast<float4*>(&Qs[h][d4]) = q;
        float4 k = *reinterpret_cast<const float4*>(base + 1024 + c4*4);
        k.x=f2tf(k.x); k.y=f2tf(k.y); k.z=f2tf(k.z); k.w=f2tf(k.w);
        *reinterpret_cast<float4*>(&Ks[h][d4]) = k;
        float4 v = *reinterpret_cast<const float4*>(base + 2048 + c4*4);
        v.x=f2tf(v.x); v.y=f2tf(v.y); v.z=f2tf(v.z); v.w=f2tf(v.w);
        *reinterpret_cast<float4*>(&Vs[h][d4]) = v;
    }
    __syncwarp();

    // S = Q K^T : m16 x n16 (2 tiles) x k64 (8 steps)
    float s[2][4] = {{0.f,0.f,0.f,0.f},{0.f,0.f,0.f,0.f}};
    #pragma unroll
    for (int ks = 0; ks < 8; ks++) {
        const int c0 = ks*8 + tg, c1 = c0 + 4;
        float a[4] = { Qs[gp][c0], Qs[gp+8][c0], Qs[gp][c1], Qs[gp+8][c1] };
        #pragma unroll
        for (int nt = 0; nt < 2; nt++) {
            float b[2] = { Ks[nt*8+gp][c0], Ks[nt*8+gp][c1] };
            mma8(s[nt], a, b);
        }
    }

    // softmax over g (exact)
    float m0 = fmaxf(fmaxf(s[0][0], s[0][1]), fmaxf(s[1][0], s[1][1]));
    float m1 = fmaxf(fmaxf(s[0][2], s[0][3]), fmaxf(s[1][2], s[1][3]));
    m0 = fmaxf(m0, __shfl_xor_sync(0xffffffffu, m0, 1));
    m0 = fmaxf(m0, __shfl_xor_sync(0xffffffffu, m0, 2));
    m1 = fmaxf(m1, __shfl_xor_sync(0xffffffffu, m1, 1));
    m1 = fmaxf(m1, __shfl_xor_sync(0xffffffffu, m1, 2));
    #pragma unroll
    for (int nt = 0; nt < 2; nt++) {
        s[nt][0] = __expf(s[nt][0] - m0);
        s[nt][1] = __expf(s[nt][1] - m0);
        s[nt][2] = __expf(s[nt][2] - m1);
        s[nt][3] = __expf(s[nt][3] - m1);
    }
    float l0 = s[0][0] + s[0][1] + s[1][0] + s[1][1];
    float l1 = s[0][2] + s[0][3] + s[1][2] + s[1][3];
    l0 += __shfl_xor_sync(0xffffffffu, l0, 1);
    l0 += __shfl_xor_sync(0xffffffffu, l0, 2);
    l1 += __shfl_xor_sync(0xffffffffu, l1, 1);
    l1 += __shfl_xor_sync(0xffffffffu, l1, 2);
    const float r0 = 1.f / l0, r1 = 1.f / l1;

    #pragma unroll
    for (int nt = 0; nt < 2; nt++) {
        *reinterpret_cast<float2*>(&Ps[gp  ][nt*8 + 2*tg]) =
            make_float2(f2tf(s[nt][0]*r0), f2tf(s[nt][1]*r0));
        *reinterpret_cast<float2*>(&Ps[gp+8][nt*8 + 2*tg]) =
            make_float2(f2tf(s[nt][2]*r1), f2tf(s[nt][3]*r1));
    }
    __syncwarp();

    // O = P V : m16 x n64 (8 tiles) x k16 (2 steps)
    float o[8][4];
    #pragma unroll
    for (int nt = 0; nt < 8; nt++)
        #pragma unroll
        for (int k = 0; k < 4; k++) o[nt][k] = 0.f;
    #pragma unroll
    for (int ks = 0; ks < 2; ks++) {
        const int c0 = ks*8 + tg, c1 = c0 + 4;
        float a[4] = { Ps[gp][c0], Ps[gp+8][c0], Ps[gp][c1], Ps[gp+8][c1] };
        #pragma unroll
        for (int nt = 0; nt < 8; nt++) {
            float b[2] = { Vs[c0][nt*8+gp], Vs[c1][nt*8+gp] };
            mma8(o[nt], a, b);
        }
    }

    // stage O (rounded) into smem, then write permuted+coalesced to g_ao
    float (*Os)[68] = Qs;   // Qs region is free now
    #pragma unroll
    for (int rr = 0; rr < 2; rr++)
        #pragma unroll
        for (int nt = 0; nt < 8; nt++)
            *reinterpret_cast<float2*>(&Os[gp + 8*rr][nt*8 + 2*tg]) =
                make_float2(f2tf(o[nt][rr*2]), f2tf(o[nt][rr*2+1]));
    __syncwarp();

    const int bidx = token >> 12;
    const int n    = token & 4095;
    const int colb = (n & 15) * 64;
    const size_t rbase = (size_t)(bidx*4096 + (n >> 4));
    #pragma unroll
    for (int i = 0; i < 8; i++) {
        const int idx = lane + 32*i;        // 0..255 = 16 rows x 16 float4
        const int h = idx >> 4, q = idx & 15;
        const int g = (q >> 2) * 16, qq = q & 3;
        float4 v = make_float4(Os[h][g + qq], Os[h][g + 4 + qq],
                               Os[h][g + 8 + qq], Os[h][g + 12 + qq]);
        *reinterpret_cast<float4*>(
            &g_ao[(rbase + (size_t)h*256) * 1024 + colb + q*4]) = v;
    }
}

// ---------------------------------------------------------------------------
// launcher
// ---------------------------------------------------------------------------
extern "C" void kernel_launch(void* const* d_in, const int* in_sizes, int n_in,
                              void* d_out, int out_size)
{
    (void)in_sizes; (void)n_in; (void)out_size;
    const float* x      = (const float*)d_in[0];  // [4,4096,1024]
    const float* w_qkv  = (const float*)d_in[1];  // [3072,1024]
    const float* w_proj = (const float*)d_in[2];  // [1024,1024]
    const float* b_proj = (const float*)d_in[3];  // [1024]
    float* out = (float*)d_out;                   // [4,4096,1024]

    cudaFuncSetAttribute(gemm_cp<0>, cudaFuncAttributeMaxDynamicSharedMemorySize, SM_GEMM);
    cudaFuncSetAttribute(gemm_cp<1>, cudaFuncAttributeMaxDynamicSharedMemorySize, SM_GEMM);
    cudaFuncSetAttribute(attn_tf32, cudaFuncAttributeMaxDynamicSharedMemorySize,
                         ATTN_SMEM_FLOATS * (int)sizeof(float));

    float* px; float* pwq; float* pwp;
    cudaGetSymbolAddress((void**)&px,  g_x);
    cudaGetSymbolAddress((void**)&pwq, g_wq);
    cudaGetSymbolAddress((void**)&pwp, g_wp);
    float* pqkv; float* pao;
    cudaGetSymbolAddress((void**)&pqkv, g_qkv);
    cudaGetSymbolAddress((void**)&pao,  g_ao);

    // 0) round (rna) + k-permute inputs
    conv_perm<<<MROWS*256/256, 256>>>(x,      px,  MROWS*256);
    conv_perm<<<NQKV *256/256, 256>>>(w_qkv,  pwq, NQKV*256);
    conv_perm<<<DMODEL*256/256, 256>>>(w_proj, pwp, DMODEL*256);

    // 1) QKV projection: g_qkv = x @ w_qkv^T
    gemm_cp<0><<<dim3(NQKV/BN2, MROWS/BM2), 256, SM_GEMM>>>(px, pwq, nullptr, pqkv, NQKV);

    // 2) per-token head attention -> g_ao (scrambled + permuted + rounded)
    attn_tf32<<<MROWS/AWARPS, AWARPS*32, ATTN_SMEM_FLOATS * sizeof(float)>>>(nullptr);

    // 3) output projection: out = g_ao @ w_proj^T + b_proj
    gemm_cp<1><<<dim3(DMODEL/BN2, MROWS/BM2), 256, SM_GEMM>>>(pao, pwp, b_proj, out, DMODEL);
}

// round 14
// speedup vs baseline: 1.4337x; 1.0187x over previous
#include <cuda_runtime.h>
#include <cstdint>

// Problem constants
#define BATCH  4
#define SEQ    4096
#define DMODEL 1024
#define NHEAD  16
#define HDIM   64
#define MROWS  (BATCH*SEQ)          // 16384
#define NQKV   (3*DMODEL)           // 3072

// Scratch (device globals: allocation-free)
__device__ float g_qkv[(size_t)MROWS * NQKV];   // 192 MB (logical layout)
__device__ float g_ao [(size_t)MROWS * DMODEL]; //  64 MB (scrambled + k-permuted + rounded)
__device__ float g_x  [(size_t)MROWS * DMODEL]; //  64 MB (rounded + k-permuted x)
__device__ float g_wq [(size_t)NQKV  * DMODEL]; //  12 MB (rounded + k-permuted w_qkv)
__device__ float g_wp [(size_t)DMODEL* DMODEL]; //   4 MB (rounded + k-permuted w_proj)

// ---------------------------------------------------------------------------
// helpers
// ---------------------------------------------------------------------------
__device__ __forceinline__ float f2tf(float x) {
    uint32_t u;
    asm("cvt.rna.tf32.f32 %0, %1;" : "=r"(u) : "f"(x));
    return __uint_as_float(u);
}

__device__ __forceinline__ uint32_t smem_u32(const void* p) {
    uint32_t a;
    asm("{ .reg .u64 t; cvta.to.shared.u64 t, %1; cvt.u32.u64 %0, t; }" : "=r"(a) : "l"(p));
    return a;
}

__device__ __forceinline__ void mma8(float c[4], const float a[4], const float b[2]) {
    uint32_t A0 = __float_as_uint(a[0]), A1 = __float_as_uint(a[1]);
    uint32_t A2 = __float_as_uint(a[2]), A3 = __float_as_uint(a[3]);
    uint32_t B0 = __float_as_uint(b[0]), B1 = __float_as_uint(b[1]);
    asm volatile(
        "mma.sync.aligned.m16n8k8.row.col.f32.tf32.tf32.f32 "
        "{%0,%1,%2,%3}, {%4,%5,%6,%7}, {%8,%9}, {%0,%1,%2,%3};"
        : "+f"(c[0]), "+f"(c[1]), "+f"(c[2]), "+f"(c[3])
        : "r"(A0), "r"(A1), "r"(A2), "r"(A3), "r"(B0), "r"(B1));
}

__device__ __forceinline__ void cp16(uint32_t dst, const void* src) {
    asm volatile("cp.async.cg.shared.global [%0], [%1], 16;" :: "r"(dst), "l"(src));
}
__device__ __forceinline__ void cp_commit() {
    asm volatile("cp.async.commit_group;" ::: "memory");
}
template<int N> __device__ __forceinline__ void cp_wait() {
    asm volatile("cp.async.wait_group %0;" :: "n"(N) : "memory");
}

// ---------------------------------------------------------------------------
// conv_perm: round to tf32 (rna) + intra-16 k-permutation, K=1024 rows.
// ---------------------------------------------------------------------------
__global__ __launch_bounds__(256)
void conv_perm(const float* __restrict__ src, float* __restrict__ dst, int nf4)
{
    int F = blockIdx.x * 256 + threadIdx.x;
    if (F >= nf4) return;
    int row = F >> 8;
    int p4  = F & 255;
    int g = p4 >> 2, qq = p4 & 3;
    const float* s = src + (size_t)row * 1024 + g * 16 + qq;
    float4 v;
    v.x = f2tf(s[0]); v.y = f2tf(s[4]); v.z = f2tf(s[8]); v.w = f2tf(s[12]);
    *reinterpret_cast<float4*>(dst + (size_t)row * 1024 + p4 * 4) = v;
}

// ---------------------------------------------------------------------------
// cp.async TF32 GEMM: C[M,N] = A[M,1024]*B[N,1024]^T (+bias)
// BM=128, BN=128, BK=32 (2 k16 panels), 8 warps (4Mx2N, warp 32x64),
// 3-stage ring (96KB, 2 CTAs/SM). Iter shape:
//   [afrag p1 prefetch, mma p0] -> bar -> [mma p1 FIRST HALF (resident)]
//   -> [load kt+2, commit, wait<1>, afrag kt+1] -> [mma p1 SECOND HALF].
// (R11 configuration — best measured: 831.9us total.)
// ---------------------------------------------------------------------------
#define BM2  128
#define BN2  128
#define STGB 32768                  // stage: A 2x8KB + B 2x8KB
#define SM_GEMM (3*STGB)            // 96 KB

template<int MODE>
__global__ __launch_bounds__(256, 2)
void gemm_cp(const float* __restrict__ A, const float* __restrict__ B,
             const float* __restrict__ bias, float* __restrict__ C, int ldc)
{
    extern __shared__ char smc[];
    const uint32_t sb = smem_u32(smc);
    const int tid  = threadIdx.x;
    const int warp = tid >> 5, lane = tid & 31;
    const int gp   = lane >> 2, tg = lane & 3;
    const int wm   = (warp & 3) * 32;        // 4 warps across M
    const int wn   = (warp >> 2) * 64;       // 2 warps across N
    const int bm   = blockIdx.y * BM2;
    const int bn   = blockIdx.x * BN2;

    auto load_stage = [&](int buf, int kt) {
        const uint32_t base = sb + buf * STGB;
        #pragma unroll
        for (int p = 0; p < 2; p++) {
            #pragma unroll
            for (int i = 0; i < 2; i++) {                // A: 128 rows x 64B
                int t = tid + 256*i; int row = t >> 2, c4 = t & 3;
                cp16(base + p*8192 + row*64 + ((c4 ^ (row & 3)) << 4),
                     A + (size_t)(bm + row)*DMODEL + kt*32 + p*16 + c4*4);
            }
            #pragma unroll
            for (int i = 0; i < 2; i++) {                // B: 128 rows x 64B
                int t = tid + 256*i; int row = t >> 2, c4 = t & 3;
                cp16(base + 16384 + p*8192 + row*64 + ((c4 ^ (row & 3)) << 4),
                     B + (size_t)(bn + row)*DMODEL + kt*32 + p*16 + c4*4);
            }
        }
    };

    // A-fragment loader: 4x LDS.128 for one k16 panel
    auto load_afrag = [&](float4* A0, float4* A8, int buf, int p) {
        const float* As = reinterpret_cast<const float*>(smc + buf*STGB + p*8192);
        #pragma unroll
        for (int mt = 0; mt < 2; mt++) {
            const int R0 = wm + mt*16 + gp;
            const int co = ((tg ^ (R0 & 3)) << 2);       // same for R0+8
            A0[mt] = *reinterpret_cast<const float4*>(As + R0*16 + co);
            A8[mt] = *reinterpret_cast<const float4*>(As + (R0+8)*16 + co);
        }
    };

    float acc[2][8][4];
    #pragma unroll
    for (int i = 0; i < 2; i++)
        #pragma unroll
        for (int j = 0; j < 8; j++)
            #pragma unroll
            for (int k = 0; k < 4; k++) acc[i][j][k] = 0.f;

    // one HALF of a panel (4 of 8 n-tiles): B 4x LDS.128 + 16 MMAs,
    // k-sub passes split so same-acc reuse distance stays 8
    auto mma_half = [&](const float4* A0, const float4* A8, int buf, int p, int half) {
        const float* Bs = reinterpret_cast<const float*>(smc + buf*STGB + 16384 + p*8192);
        float4 Bf[4];
        #pragma unroll
        for (int j = 0; j < 4; j++) {
            const int R = wn + (half*4 + j)*8 + gp;
            Bf[j] = *reinterpret_cast<const float4*>(Bs + R*16 + ((tg ^ (R & 3)) << 2));
        }
        #pragma unroll
        for (int j = 0; j < 4; j++) {
            const int nt = half*4 + j;
            #pragma unroll
            for (int mt = 0; mt < 2; mt++) {
                const float a0[4] = { A0[mt].x, A8[mt].x, A0[mt].y, A8[mt].y };
                const float b0[2] = { Bf[j].x, Bf[j].y };
                mma8(acc[mt][nt], a0, b0);
            }
        }
        #pragma unroll
        for (int j = 0; j < 4; j++) {
            const int nt = half*4 + j;
            #pragma unroll
            for (int mt = 0; mt < 2; mt++) {
                const float a1[4] = { A0[mt].z, A8[mt].z, A0[mt].w, A8[mt].w };
                const float b1[2] = { Bf[j].z, Bf[j].w };
                mma8(acc[mt][nt], a1, b1);
            }
        }
    };

    load_stage(0, 0); cp_commit();
    load_stage(1, 1); cp_commit();
    cp_wait<1>();            // stage 0 resident
    __syncthreads();

    float4 Aa0[2], Aa8[2], Ab0[2], Ab8[2];
    load_afrag(Aa0, Aa8, 0, 0);              // A(stage0, p0)

    const int NI = DMODEL / 32;    // 32
    int buf = 0;
    for (int kt = 0; kt < NI; kt++) {
        // ---- panel 0 of stage kt: prefetch A(kt,p1), mma with Aa
        load_afrag(Ab0, Ab8, buf, 1);
        mma_half(Aa0, Aa8, buf, 0, 0);
        mma_half(Aa0, Aa8, buf, 0, 1);

        __syncthreads();                     // stage kt-1 drained by all warps

        // ---- panel 1 first half: tensor work immediately (Ab resident)
        mma_half(Ab0, Ab8, buf, 1, 0);

        // ---- cp.async prefix + wait overlap p1's HMMA drain
        if (kt + 2 < NI) load_stage((buf + 2) % 3, kt + 2);
        cp_commit();
        cp_wait<1>();                        // stage kt+1 resident (kt+2 streams)

        // ---- next-iter A-frags + p1 second half (hides the LDS)
        const int nbuf = (buf + 1) % 3;
        load_afrag(Aa0, Aa8, nbuf, 0);
        mma_half(Ab0, Ab8, buf, 1, 1);
        buf = nbuf;
    }

    // epilogue: direct float2 stores
    #pragma unroll
    for (int mt = 0; mt < 2; mt++) {
        #pragma unroll
        for (int nt = 0; nt < 8; nt++) {
            const int col = bn + wn + nt*8 + 2*tg;
            float bx = 0.f, by = 0.f;
            if (MODE == 1) {
                float2 bv = *reinterpret_cast<const float2*>(&bias[col]);
                bx = bv.x; by = bv.y;
            }
            #pragma unroll
            for (int rr = 0; rr < 2; rr++) {
                const int row = bm + wm + mt*16 + gp + rr*8;
                *reinterpret_cast<float2*>(&C[(size_t)row*ldc + col]) =
                    make_float2(acc[mt][nt][rr*2] + bx, acc[mt][nt][rr*2+1] + by);
            }
        }
    }
}

// ---------------------------------------------------------------------------
// Per-token head attention (einsum over HEADS, per token). One warp/token.
// Writes g_ao in the scrambled swapaxes layout, tf32-rounded AND k-permuted.
// AWARPS=4: CTA smem 57.3KB -> 3 CTAs/SM -> 12 resident warps (was 8).
// ---------------------------------------------------------------------------
#define AWARPS 4
#define ATTN_SMEM_FLOATS (AWARPS * (3*16*68 + 16*20))   // 14336 floats = 57344 B

__global__ __launch_bounds__(AWARPS*32)
void attn_tf32(float* __restrict__ dummy)
{
    extern __shared__ float sm[];
    const int warp = threadIdx.x >> 5, lane = threadIdx.x & 31;
    const int gp = lane >> 2, tg = lane & 3;

    float* wsm = sm + warp * (3*16*68 + 16*20);
    float (*Qs)[68] = reinterpret_cast<float(*)[68]>(wsm);
    float (*Ks)[68] = reinterpret_cast<float(*)[68]>(wsm + 1088);
    float (*Vs)[68] = reinterpret_cast<float(*)[68]>(wsm + 2176);
    float (*Ps)[20] = reinterpret_cast<float(*)[20]>(wsm + 3264);
    (void)dummy;

    const int token = blockIdx.x * AWARPS + warp;
    const float* base = g_qkv + (size_t)token * NQKV;
    const float scale = 0.125f;   // HD^-0.5

    #pragma unroll
    for (int j = 0; j < 8; j++) {
        const int c4 = lane + j*32;
        const int h  = c4 >> 4;
        const int d4 = (c4 & 15) * 4;
        float4 q = *reinterpret_cast<const float4*>(base + c4*4);
        q.x=f2tf(q.x*scale); q.y=f2tf(q.y*scale); q.z=f2tf(q.z*scale); q.w=f2tf(q.w*scale);
        *reinterpret_cast<float4*>(&Qs[h][d4]) = q;
        float4 k = *reinterpret_cast<const float4*>(base + 1024 + c4*4);
        k.x=f2tf(k.x); k.y=f2tf(k.y); k.z=f2tf(k.z); k.w=f2tf(k.w);
        *reinterpret_cast<float4*>(&Ks[h][d4]) = k;
        float4 v = *reinterpret_cast<const float4*>(base + 2048 + c4*4);
        v.x=f2tf(v.x); v.y=f2tf(v.y); v.z=f2tf(v.z); v.w=f2tf(v.w);
        *reinterpret_cast<float4*>(&Vs[h][d4]) = v;
    }
    __syncwarp();

    // S = Q K^T : m16 x n16 (2 tiles) x k64 (8 steps)
    float s[2][4] = {{0.f,0.f,0.f,0.f},{0.f,0.f,0.f,0.f}};
    #pragma unroll
    for (int ks = 0; ks < 8; ks++) {
        const int c0 = ks*8 + tg, c1 = c0 + 4;
        float a[4] = { Qs[gp][c0], Qs[gp+8][c0], Qs[gp][c1], Qs[gp+8][c1] };
        #pragma unroll
        for (int nt = 0; nt < 2; nt++) {
            float b[2] = { Ks[nt*8+gp][c0], Ks[nt*8+gp][c1] };
            mma8(s[nt], a, b);
        }
    }

    // softmax over g (exact)
    float m0 = fmaxf(fmaxf(s[0][0], s[0][1]), fmaxf(s[1][0], s[1][1]));
    float m1 = fmaxf(fmaxf(s[0][2], s[0][3]), fmaxf(s[1][2], s[1][3]));
    m0 = fmaxf(m0, __shfl_xor_sync(0xffffffffu, m0, 1));
    m0 = fmaxf(m0, __shfl_xor_sync(0xffffffffu, m0, 2));
    m1 = fmaxf(m1, __shfl_xor_sync(0xffffffffu, m1, 1));
    m1 = fmaxf(m1, __shfl_xor_sync(0xffffffffu, m1, 2));
    #pragma unroll
    for (int nt = 0; nt < 2; nt++) {
        s[nt][0] = __expf(s[nt][0] - m0);
        s[nt][1] = __expf(s[nt][1] - m0);
        s[nt][2] = __expf(s[nt][2] - m1);
        s[nt][3] = __expf(s[nt][3] - m1);
    }
    float l0 = s[0][0] + s[0][1] + s[1][0] + s[1][1];
    float l1 = s[0][2] + s[0][3] + s[1][2] + s[1][3];
    l0 += __shfl_xor_sync(0xffffffffu, l0, 1);
    l0 += __shfl_xor_sync(0xffffffffu, l0, 2);
    l1 += __shfl_xor_sync(0xffffffffu, l1, 1);
    l1 += __shfl_xor_sync(0xffffffffu, l1, 2);
    const float r0 = 1.f / l0, r1 = 1.f / l1;

    #pragma unroll
    for (int nt = 0; nt < 2; nt++) {
        *reinterpret_cast<float2*>(&Ps[gp  ][nt*8 + 2*tg]) =
            make_float2(f2tf(s[nt][0]*r0), f2tf(s[nt][1]*r0));
        *reinterpret_cast<float2*>(&Ps[gp+8][nt*8 + 2*tg]) =
            make_float2(f2tf(s[nt][2]*r1), f2tf(s[nt][3]*r1));
    }
    __syncwarp();

    // O = P V : m16 x n64 (8 tiles) x k16 (2 steps)
    float o[8][4];
    #pragma unroll
    for (int nt = 0; nt < 8; nt++)
        #pragma unroll
        for (int k = 0; k < 4; k++) o[nt][k] = 0.f;
    #pragma unroll
    for (int ks = 0; ks < 2; ks++) {
        const int c0 = ks*8 + tg, c1 = c0 + 4;
        float a[4] = { Ps[gp][c0], Ps[gp+8][c0], Ps[gp][c1], Ps[gp+8][c1] };
        #pragma unroll
        for (int nt = 0; nt < 8; nt++) {
            float b[2] = { Vs[c0][nt*8+gp], Vs[c1][nt*8+gp] };
            mma8(o[nt], a, b);
        }
    }

    // stage O (rounded) into smem, then write permuted+coalesced to g_ao
    float (*Os)[68] = Qs;   // Qs region is free now
    #pragma unroll
    for (int rr = 0; rr < 2; rr++)
        #pragma unroll
        for (int nt = 0; nt < 8; nt++)
            *reinterpret_cast<float2*>(&Os[gp + 8*rr][nt*8 + 2*tg]) =
                make_float2(f2tf(o[nt][rr*2]), f2tf(o[nt][rr*2+1]));
    __syncwarp();

    const int bidx = token >> 12;
    const int n    = token & 4095;
    const int colb = (n & 15) * 64;
    const size_t rbase = (size_t)(bidx*4096 + (n >> 4));
    #pragma unroll
    for (int i = 0; i < 8; i++) {
        const int idx = lane + 32*i;        // 0..255 = 16 rows x 16 float4
        const int h = idx >> 4, q = idx & 15;
        const int g = (q >> 2) * 16, qq = q & 3;
        float4 v = make_float4(Os[h][g + qq], Os[h][g + 4 + qq],
                               Os[h][g + 8 + qq], Os[h][g + 12 + qq]);
        *reinterpret_cast<float4*>(
            &g_ao[(rbase + (size_t)h*256) * 1024 + colb + q*4]) = v;
    }
}

// ---------------------------------------------------------------------------
// launcher
// ---------------------------------------------------------------------------
extern "C" void kernel_launch(void* const* d_in, const int* in_sizes, int n_in,
                              void* d_out, int out_size)
{
    (void)in_sizes; (void)n_in; (void)out_size;
    const float* x      = (const float*)d_in[0];  // [4,4096,1024]
    const float* w_qkv  = (const float*)d_in[1];  // [3072,1024]
    const float* w_proj = (const float*)d_in[2];  // [1024,1024]
    const float* b_proj = (const float*)d_in[3];  // [1024]
    float* out = (float*)d_out;                   // [4,4096,1024]

    cudaFuncSetAttribute(gemm_cp<0>, cudaFuncAttributeMaxDynamicSharedMemorySize, SM_GEMM);
    cudaFuncSetAttribute(gemm_cp<1>, cudaFuncAttributeMaxDynamicSharedMemorySize, SM_GEMM);
    cudaFuncSetAttribute(attn_tf32, cudaFuncAttributeMaxDynamicSharedMemorySize,
                         ATTN_SMEM_FLOATS * (int)sizeof(float));

    float* px; float* pwq; float* pwp;
    cudaGetSymbolAddress((void**)&px,  g_x);
    cudaGetSymbolAddress((void**)&pwq, g_wq);
    cudaGetSymbolAddress((void**)&pwp, g_wp);
    float* pqkv; float* pao;
    cudaGetSymbolAddress((void**)&pqkv, g_qkv);
    cudaGetSymbolAddress((void**)&pao,  g_ao);

    // 0) round (rna) + k-permute inputs
    conv_perm<<<MROWS*256/256, 256>>>(x,      px,  MROWS*256);
    conv_perm<<<NQKV *256/256, 256>>>(w_qkv,  pwq, NQKV*256);
    conv_perm<<<DMODEL*256/256, 256>>>(w_proj, pwp, DMODEL*256);

    // 1) QKV projection: g_qkv = x @ w_qkv^T
    gemm_cp<0><<<dim3(NQKV/BN2, MROWS/BM2), 256, SM_GEMM>>>(px, pwq, nullptr, pqkv, NQKV);

    // 2) per-token head attention -> g_ao (scrambled + permuted + rounded)
    attn_tf32<<<MROWS/AWARPS, AWARPS*32, ATTN_SMEM_FLOATS * sizeof(float)>>>(nullptr);

    // 3) output projection: out = g_ao @ w_proj^T + b_proj
    gemm_cp<1><<<dim3(DMODEL/BN2, MROWS/BM2), 256, SM_GEMM>>>(pao, pwp, b_proj, out, DMODEL);
}